// round 3
// baseline (speedup 1.0000x reference)
#include <cuda_runtime.h>
#include <cuda_bf16.h>

typedef unsigned long long ull;

#define NCTAS 128
#define NT    512
#define ROWS  32
#define RS    34          // padded row stride (floats) for h / x buffers
#define HH    256
#define EE    64
#define VV    64
#define ZZ    128
#define TS    119
#define KT    8
#define GATES 768

struct SM {
    float hb[3][HH][RS];        // hidden state, k-major, row-padded
    float xz[ZZ][RS];           // z at init / embedding x per step
    float wt[2][KT][GATES];     // double-buffered weight k-tiles
    float br[3][HH];            // b_ih_r + b_hh_r
    float bz[3][HH];            // b_ih_z + b_hh_z
    float bin_[3][HH];          // b_ih_n
    float bhn_[3][HH];          // b_hh_n
    float lbuf[ROWS][VV + 1];   // logits for argmax (padded)
    int   tok[ROWS];
};

// ---------------- packed f32x2 helpers ----------------
__device__ __forceinline__ ull dup2(float v) {
    ull r; asm("mov.b64 %0, {%1, %1};" : "=l"(r) : "f"(v)); return r;
}
__device__ __forceinline__ void fma2(ull& d, ull a, ull b) {
    asm("fma.rn.f32x2 %0, %1, %2, %0;" : "+l"(d) : "l"(a), "l"(b));
}
__device__ __forceinline__ float f2lo(ull v) { return __uint_as_float((unsigned)(v & 0xffffffffULL)); }
__device__ __forceinline__ float f2hi(ull v) { return __uint_as_float((unsigned)(v >> 32)); }

// ---------------- flag-proof ~1ulp activations ----------------
// exp built from explicit FMAs: Cody-Waite reduction + degree-6 Horner + exponent scale.
// Immune to --use_fast_math (no libcall, no division).
__device__ __forceinline__ float exp_acc(float x) {
    x = fminf(fmaxf(x, -87.0f), 87.0f);
    float n = rintf(x * 1.4426950408889634f);
    float r = fmaf(n, -6.93145752e-01f, x);        // ln2_hi (trailing zeros)
    r = fmaf(n, -1.42860677e-06f, r);              // ln2_lo
    float p = 1.98412698412e-4f;                   // 1/5040
    p = fmaf(p, r, 1.38888888889e-3f);             // 1/720
    p = fmaf(p, r, 8.33333333333e-3f);             // 1/120
    p = fmaf(p, r, 4.16666666667e-2f);             // 1/24
    p = fmaf(p, r, 1.66666666667e-1f);             // 1/6
    p = fmaf(p, r, 0.5f);
    p = fmaf(p, r, 1.0f);
    p = fmaf(p, r, 1.0f);
    float sc = __int_as_float(((int)n + 127) << 23);
    return p * sc;
}
__device__ __forceinline__ float sigm(float x) {
    float e = exp_acc(-x);
    return __fdiv_rn(1.0f, 1.0f + e);              // IEEE div regardless of flags
}
__device__ __forceinline__ float mytanh(float x) {
    float a = fabsf(x);
    float e = exp_acc(-2.0f * a);
    float r = __fdiv_rn(1.0f - e, 1.0f + e);
    return copysignf(r, x);
}

// ---------------- weight tile staging (768 rows x KT k's) ----------------
__device__ __forceinline__ void ldg_tile(const float* __restrict__ W, int ldk, int kb,
                                         float4 (&rg)[4], int tid) {
    const float4* p = (const float4*)(W + (size_t)tid * ldk + kb);
    rg[0] = p[0]; rg[1] = p[1];
    if (tid < GATES - NT) {
        const float4* q = (const float4*)(W + (size_t)(tid + NT) * ldk + kb);
        rg[2] = q[0]; rg[3] = q[1];
    }
}
__device__ __forceinline__ void sts_tile(float* wtb, const float4 (&rg)[4], int tid) {
    float* d = wtb + tid;
    d[0 * GATES] = rg[0].x; d[1 * GATES] = rg[0].y; d[2 * GATES] = rg[0].z; d[3 * GATES] = rg[0].w;
    d[4 * GATES] = rg[1].x; d[5 * GATES] = rg[1].y; d[6 * GATES] = rg[1].z; d[7 * GATES] = rg[1].w;
    if (tid < GATES - NT) {
        float* e = wtb + tid + NT;
        e[0 * GATES] = rg[2].x; e[1 * GATES] = rg[2].y; e[2 * GATES] = rg[2].z; e[3 * GATES] = rg[2].w;
        e[4 * GATES] = rg[3].x; e[5 * GATES] = rg[3].y; e[6 * GATES] = rg[3].z; e[7 * GATES] = rg[3].w;
    }
}

// GEMM phase: acc[SA/SB/SC] (j0, j0+1) x (4 row pairs) += W[768][K] slice * x[K][ROWS]
template<int SA, int SB, int SC>
__device__ __forceinline__ void gemm768(SM* s, const float* __restrict__ W, int ldk, int K,
                                        const float* __restrict__ xsrc, ull (&acc)[4][2][4],
                                        int tid, int j0, int rp0)
{
    int nt = K / KT;
    float4 rg[4];
    ldg_tile(W, ldk, 0, rg, tid);
    for (int tile = 0; tile < nt; tile++) {
        float* wtb = &s->wt[tile & 1][0][0];
        sts_tile(wtb, rg, tid);
        __syncthreads();
        if (tile + 1 < nt) ldg_tile(W, ldk, (tile + 1) * KT, rg, tid);
        const float* xb = xsrc + tile * KT * RS + rp0 * 2;
#pragma unroll
        for (int kk = 0; kk < KT; kk++) {
            const ull* xp = (const ull*)(xb + kk * RS);
            ull xv0 = xp[0], xv1 = xp[1], xv2 = xp[2], xv3 = xp[3];
            const float* wr = wtb + kk * GATES + j0;
            float2 wA = *(const float2*)(wr);
            float2 wB = *(const float2*)(wr + 256);
            float2 wC = *(const float2*)(wr + 512);
            ull a0 = dup2(wA.x), a1 = dup2(wA.y);
            ull b0 = dup2(wB.x), b1 = dup2(wB.y);
            ull c0 = dup2(wC.x), c1 = dup2(wC.y);
            fma2(acc[SA][0][0], a0, xv0); fma2(acc[SA][0][1], a0, xv1);
            fma2(acc[SA][0][2], a0, xv2); fma2(acc[SA][0][3], a0, xv3);
            fma2(acc[SA][1][0], a1, xv0); fma2(acc[SA][1][1], a1, xv1);
            fma2(acc[SA][1][2], a1, xv2); fma2(acc[SA][1][3], a1, xv3);
            fma2(acc[SB][0][0], b0, xv0); fma2(acc[SB][0][1], b0, xv1);
            fma2(acc[SB][0][2], b0, xv2); fma2(acc[SB][0][3], b0, xv3);
            fma2(acc[SB][1][0], b1, xv0); fma2(acc[SB][1][1], b1, xv1);
            fma2(acc[SB][1][2], b1, xv2); fma2(acc[SB][1][3], b1, xv3);
            fma2(acc[SC][0][0], c0, xv0); fma2(acc[SC][0][1], c0, xv1);
            fma2(acc[SC][0][2], c0, xv2); fma2(acc[SC][0][3], c0, xv3);
            fma2(acc[SC][1][0], c1, xv0); fma2(acc[SC][1][1], c1, xv1);
            fma2(acc[SC][1][2], c1, xv2); fma2(acc[SC][1][3], c1, xv3);
        }
        // one barrier per tile: this buffer is only overwritten two tiles later,
        // after the next barrier.
    }
}

// One GRU layer step for layer l.
__device__ __forceinline__ void layer_step(SM* s, const float* __restrict__ xsrc, int Kin,
                                           const float* __restrict__ wi,
                                           const float* __restrict__ wh,
                                           int l, int tid, int j0, int rp0)
{
    ull acc[4][2][4];
#pragma unroll
    for (int jj = 0; jj < 2; jj++) {
        ull b0 = dup2(s->br[l][j0 + jj]);
        ull b1 = dup2(s->bz[l][j0 + jj]);
        ull b2 = dup2(s->bin_[l][j0 + jj]);
        ull b3 = dup2(s->bhn_[l][j0 + jj]);
#pragma unroll
        for (int p = 0; p < 4; p++) {
            acc[0][jj][p] = b0; acc[1][jj][p] = b1;
            acc[2][jj][p] = b2; acc[3][jj][p] = b3;
        }
    }
    gemm768<0, 1, 2>(s, wi, Kin, Kin, xsrc, acc, tid, j0, rp0);          // x @ wi^T
    gemm768<0, 1, 3>(s, wh, HH, HH, &s->hb[l][0][0], acc, tid, j0, rp0); // h @ wh^T
    __syncthreads();   // all reads of hb[l] done before overwrite
#pragma unroll
    for (int jj = 0; jj < 2; jj++) {
#pragma unroll
        for (int p = 0; p < 4; p++) {
            float2 hold = *(const float2*)&s->hb[l][j0 + jj][(rp0 + p) * 2];
            float rlo = sigm(f2lo(acc[0][jj][p])), rhi = sigm(f2hi(acc[0][jj][p]));
            float ulo = sigm(f2lo(acc[1][jj][p])), uhi = sigm(f2hi(acc[1][jj][p]));
            float nlo = mytanh(f2lo(acc[2][jj][p]) + rlo * f2lo(acc[3][jj][p]));
            float nhi = mytanh(f2hi(acc[2][jj][p]) + rhi * f2hi(acc[3][jj][p]));
            float2 hnew;
            hnew.x = (1.0f - ulo) * nlo + ulo * hold.x;
            hnew.y = (1.0f - uhi) * nhi + uhi * hold.y;
            *(float2*)&s->hb[l][j0 + jj][(rp0 + p) * 2] = hnew;
        }
    }
    __syncthreads();   // new hb[l] visible
}

__global__ void __launch_bounds__(NT, 1) moldec_kernel(
    const float* __restrict__ z,     const float* __restrict__ emb,
    const float* __restrict__ z2h_w, const float* __restrict__ z2h_b,
    const float* __restrict__ out_w, const float* __restrict__ out_b,
    const float* __restrict__ wi0, const float* __restrict__ wh0,
    const float* __restrict__ bi0, const float* __restrict__ bh0,
    const float* __restrict__ wi1, const float* __restrict__ wh1,
    const float* __restrict__ bi1, const float* __restrict__ bh1,
    const float* __restrict__ wi2, const float* __restrict__ wh2,
    const float* __restrict__ bi2, const float* __restrict__ bh2,
    float* __restrict__ out)
{
    extern __shared__ char smraw[];
    SM* s = (SM*)smraw;
    const int tid = threadIdx.x;
    const int row0 = blockIdx.x * ROWS;
    const int og = tid & 127;
    const int j0 = og * 2;
    const int rg = tid >> 7;
    const int rp0 = rg * 4;

    // combined biases
    {
        const float* bip[3] = {bi0, bi1, bi2};
        const float* bhp[3] = {bh0, bh1, bh2};
        for (int i = tid; i < 3 * HH; i += NT) {
            int l = i >> 8, j = i & 255;
            s->br[l][j]   = bip[l][j]          + bhp[l][j];
            s->bz[l][j]   = bip[l][HH + j]     + bhp[l][HH + j];
            s->bin_[l][j] = bip[l][2 * HH + j];
            s->bhn_[l][j] = bhp[l][2 * HH + j];
        }
    }
    // stage z transposed (k-major)
    for (int i = tid; i < ZZ * ROWS; i += NT) {
        int r = i >> 7, k = i & 127;
        s->xz[k][r] = z[(size_t)(row0 + r) * ZZ + k];
    }
    if (tid < ROWS) s->tok[tid] = 1;
    __syncthreads();

    // initial hidden: h0 = tanh(z @ z2h_w^T + z2h_b)
    {
        ull acc[4][2][4];
#pragma unroll
        for (int ss = 0; ss < 3; ss++) {
#pragma unroll
            for (int jj = 0; jj < 2; jj++) {
                ull b = dup2(z2h_b[ss * 256 + j0 + jj]);
#pragma unroll
                for (int p = 0; p < 4; p++) acc[ss][jj][p] = b;
            }
        }
#pragma unroll
        for (int jj = 0; jj < 2; jj++)
#pragma unroll
            for (int p = 0; p < 4; p++) acc[3][jj][p] = 0ULL;

        gemm768<0, 1, 2>(s, z2h_w, ZZ, ZZ, &s->xz[0][0], acc, tid, j0, rp0);
        __syncthreads();
#pragma unroll
        for (int ss = 0; ss < 3; ss++)
#pragma unroll
            for (int jj = 0; jj < 2; jj++)
#pragma unroll
                for (int p = 0; p < 4; p++) {
                    float2 hv;
                    hv.x = mytanh(f2lo(acc[ss][jj][p]));
                    hv.y = mytanh(f2hi(acc[ss][jj][p]));
                    *(float2*)&s->hb[ss][j0 + jj][(rp0 + p) * 2] = hv;
                }
        __syncthreads();
    }

    // decode loop
    for (int t = 0; t < TS; t++) {
        for (int i = tid; i < EE * ROWS; i += NT) {
            int r = i >> 6, k = i & 63;
            s->xz[k][r] = emb[(size_t)s->tok[r] * EE + k];
        }
        // visibility via gemm768's first tile barrier

        layer_step(s, &s->xz[0][0],    EE, wi0, wh0, 0, tid, j0, rp0);
        layer_step(s, &s->hb[0][0][0], HH, wi1, wh1, 1, tid, j0, rp0);
        layer_step(s, &s->hb[1][0][0], HH, wi2, wh2, 2, tid, j0, rp0);

        // output projection: logits = hb[2] @ out_w^T + out_b
        {
            const int v = tid & 63;
            const int rg2 = tid >> 6;
            const int rpo = rg2 * 2;
            ull oa0 = dup2(out_b[v]);
            ull oa1 = oa0;
            const float* xs = &s->hb[2][0][0];
            float4 r4[2];
            if (tid < VV) {
                const float4* p = (const float4*)(out_w + (size_t)tid * HH);
                r4[0] = p[0]; r4[1] = p[1];
            }
            for (int tile = 0; tile < HH / KT; tile++) {
                float* wtb = &s->wt[tile & 1][0][0];
                if (tid < VV) {
                    float* d = wtb + tid;
                    d[0 * GATES] = r4[0].x; d[1 * GATES] = r4[0].y;
                    d[2 * GATES] = r4[0].z; d[3 * GATES] = r4[0].w;
                    d[4 * GATES] = r4[1].x; d[5 * GATES] = r4[1].y;
                    d[6 * GATES] = r4[1].z; d[7 * GATES] = r4[1].w;
                }
                __syncthreads();
                if (tid < VV && tile + 1 < HH / KT) {
                    const float4* p = (const float4*)(out_w + (size_t)tid * HH + (tile + 1) * KT);
                    r4[0] = p[0]; r4[1] = p[1];
                }
                const float* xb = xs + tile * KT * RS + rpo * 2;
#pragma unroll
                for (int kk = 0; kk < KT; kk++) {
                    const ull* xp = (const ull*)(xb + kk * RS);
                    ull w = dup2(wtb[kk * GATES + v]);
                    fma2(oa0, w, xp[0]);
                    fma2(oa1, w, xp[1]);
                }
            }
#pragma unroll
            for (int p = 0; p < 2; p++) {
                ull a = p ? oa1 : oa0;
                int r0p = (rpo + p) * 2;
                s->lbuf[r0p][v]     = f2lo(a);
                s->lbuf[r0p + 1][v] = f2hi(a);
                out[((size_t)(row0 + r0p) * TS + t) * VV + v]     = f2lo(a);
                out[((size_t)(row0 + r0p + 1) * TS + t) * VV + v] = f2hi(a);
            }
        }
        __syncthreads();
        // per-row argmax (first-max tie rule, matches jnp.argmax)
        if (tid < ROWS) {
            float m = s->lbuf[tid][0];
            int am = 0;
#pragma unroll 8
            for (int vv = 1; vv < VV; vv++) {
                float val = s->lbuf[tid][vv];
                if (val > m) { m = val; am = vv; }
            }
            s->tok[tid] = am;
        }
        __syncthreads();
    }
}

extern "C" void kernel_launch(void* const* d_in, const int* in_sizes, int n_in,
                              void* d_out, int out_size)
{
    const float* z     = (const float*)d_in[0];
    const float* emb   = (const float*)d_in[1];
    const float* z2h_w = (const float*)d_in[2];
    const float* z2h_b = (const float*)d_in[3];
    const float* out_w = (const float*)d_in[4];
    const float* out_b = (const float*)d_in[5];
    const float* wi0 = (const float*)d_in[6];
    const float* wh0 = (const float*)d_in[7];
    const float* bi0 = (const float*)d_in[8];
    const float* bh0 = (const float*)d_in[9];
    const float* wi1 = (const float*)d_in[10];
    const float* wh1 = (const float*)d_in[11];
    const float* bi1 = (const float*)d_in[12];
    const float* bh1 = (const float*)d_in[13];
    const float* wi2 = (const float*)d_in[14];
    const float* wh2 = (const float*)d_in[15];
    const float* bi2 = (const float*)d_in[16];
    const float* bh2 = (const float*)d_in[17];
    float* out = (float*)d_out;

    cudaFuncSetAttribute(moldec_kernel, cudaFuncAttributeMaxDynamicSharedMemorySize,
                         (int)sizeof(SM));
    moldec_kernel<<<NCTAS, NT, sizeof(SM)>>>(
        z, emb, z2h_w, z2h_b, out_w, out_b,
        wi0, wh0, bi0, bh0,
        wi1, wh1, bi1, bh1,
        wi2, wh2, bi2, bh2,
        out);
}

// round 4
// speedup vs baseline: 1.3849x; 1.3849x over previous
#include <cuda_runtime.h>
#include <cuda_bf16.h>

typedef unsigned long long ull;

#define NCTAS 147
#define NT    512
#define ROWS  28          // rows per CTA (last CTA partially valid)
#define NPAIR 7           // row pairs per thread (half of 14 rows)
#define RS    30          // padded row stride (floats), 8B-aligned per k
#define HH    256
#define EE    64
#define VV    64
#define ZZ    128
#define TS    119
#define BTOT  4096

// Transposed weight scratch: wT[k][j][4] = (w_r[j][k], w_z[j][k], w_n[j][k], 0)
// k-slot bases: L0 wi:0(K=64) wh:64 | L1 wi:320 wh:576 | L2 wi:832 wh:1088 | total 1344
__device__ float4 g_wT[1344 * 256];
__device__ float4 g_z2h[128 * 256];     // z2h: [k][j][4] = (row j, 256+j, 512+j)
__device__ float  g_owT[256 * 64];      // out_w transposed: [k][v]

struct SM {
    float hb[3][HH][RS];        // hidden state, k-major
    float xz[ZZ][RS];           // z at init / embedding per step
    float br[3][HH];            // b_ih_r + b_hh_r
    float bz[3][HH];            // b_ih_z + b_hh_z
    float bin_[3][HH];          // b_ih_n
    float bhn_[3][HH];          // b_hh_n
    float lbuf[ROWS][VV + 1];   // logits for argmax
    int   tok[ROWS];
};

// ---------------- packed f32x2 helpers ----------------
__device__ __forceinline__ ull dup2(float v) {
    ull r; asm("mov.b64 %0, {%1, %1};" : "=l"(r) : "f"(v)); return r;
}
__device__ __forceinline__ void fma2(ull& d, ull a, ull b) {
    asm("fma.rn.f32x2 %0, %1, %2, %0;" : "+l"(d) : "l"(a), "l"(b));
}
__device__ __forceinline__ float f2lo(ull v) { return __uint_as_float((unsigned)(v & 0xffffffffULL)); }
__device__ __forceinline__ float f2hi(ull v) { return __uint_as_float((unsigned)(v >> 32)); }

// ---------------- flag-proof ~1ulp activations ----------------
__device__ __forceinline__ float exp_acc(float x) {
    x = fminf(fmaxf(x, -87.0f), 87.0f);
    float n = rintf(x * 1.4426950408889634f);
    float r = fmaf(n, -6.93145752e-01f, x);
    r = fmaf(n, -1.42860677e-06f, r);
    float p = 1.98412698412e-4f;
    p = fmaf(p, r, 1.38888888889e-3f);
    p = fmaf(p, r, 8.33333333333e-3f);
    p = fmaf(p, r, 4.16666666667e-2f);
    p = fmaf(p, r, 1.66666666667e-1f);
    p = fmaf(p, r, 0.5f);
    p = fmaf(p, r, 1.0f);
    p = fmaf(p, r, 1.0f);
    float sc = __int_as_float(((int)n + 127) << 23);
    return p * sc;
}
__device__ __forceinline__ float sigm(float x) {
    float e = exp_acc(-x);
    return __fdiv_rn(1.0f, 1.0f + e);
}
__device__ __forceinline__ float mytanh(float x) {
    float a = fabsf(x);
    float e = exp_acc(-2.0f * a);
    float r = __fdiv_rn(1.0f - e, 1.0f + e);
    return copysignf(r, x);
}

// ---------------- prep kernel: weight transposes ----------------
__global__ void prep_kernel(
    const float* __restrict__ wi0, const float* __restrict__ wh0,
    const float* __restrict__ wi1, const float* __restrict__ wh1,
    const float* __restrict__ wi2, const float* __restrict__ wh2,
    const float* __restrict__ z2h_w, const float* __restrict__ out_w)
{
    int bx = blockIdx.x;
    int j = threadIdx.x;
    if (bx < 1344) {
        const float* W; int ld, kk;
        if      (bx <   64) { W = wi0; ld =  64; kk = bx;        }
        else if (bx <  320) { W = wh0; ld = 256; kk = bx -   64; }
        else if (bx <  576) { W = wi1; ld = 256; kk = bx -  320; }
        else if (bx <  832) { W = wh1; ld = 256; kk = bx -  576; }
        else if (bx < 1088) { W = wi2; ld = 256; kk = bx -  832; }
        else                { W = wh2; ld = 256; kk = bx - 1088; }
        float4 v;
        v.x = W[(size_t)j * ld + kk];
        v.y = W[(size_t)(256 + j) * ld + kk];
        v.z = W[(size_t)(512 + j) * ld + kk];
        v.w = 0.0f;
        g_wT[bx * 256 + j] = v;
    } else if (bx < 1472) {
        int kz = bx - 1344;
        float4 v;
        v.x = z2h_w[(size_t)j * ZZ + kz];
        v.y = z2h_w[(size_t)(256 + j) * ZZ + kz];
        v.z = z2h_w[(size_t)(512 + j) * ZZ + kz];
        v.w = 0.0f;
        g_z2h[kz * 256 + j] = v;
    } else {
        int m = bx - 1472;                 // 0..63
        int id = m * 256 + j;              // 0..16383
        int k = id >> 6, v = id & 63;
        g_owT[k * 64 + v] = out_w[(size_t)v * HH + k];
    }
}

// ---------------- GEMM phase: thread owns gate j, NPAIR row-pairs ----------------
// wbase: float4 slots [K][256]; sections (x,y,z) -> acc rows (0,1,SN).
template<int K, int SN>
__device__ __forceinline__ void gemm_phase(const float4* __restrict__ wbase,
                                           const float* __restrict__ xb,
                                           ull (&acc)[4][NPAIR], int j)
{
    const float4* wp = wbase + j;
    float4 w0 = wp[0];
    float4 w1 = wp[256];
    const float4* wpp = wp + 512;
#pragma unroll 2
    for (int k = 0; k < K; k++) {
        float4 wc = w0;
        w0 = w1;
        if (k + 2 < K) w1 = wpp[0];
        wpp += 256;
        const ull* xp = (const ull*)(xb + (size_t)k * RS);
        ull wr = dup2(wc.x), wz = dup2(wc.y), wn = dup2(wc.z);
#pragma unroll
        for (int p = 0; p < NPAIR; p++) {
            ull xv = xp[p];
            fma2(acc[0][p], wr, xv);
            fma2(acc[1][p], wz, xv);
            fma2(acc[SN][p], wn, xv);
        }
    }
}

// One GRU layer step. xb/hbl already offset by rh*14.
template<int KIN>
__device__ __forceinline__ void layer_stepB(SM* s, const float* __restrict__ xb,
                                            const float4* __restrict__ wTi,
                                            const float4* __restrict__ wTh,
                                            int l, int j, int rh)
{
    ull acc[4][NPAIR];
    {
        ull b0 = dup2(s->br[l][j]);
        ull b1 = dup2(s->bz[l][j]);
        ull b2 = dup2(s->bin_[l][j]);
        ull b3 = dup2(s->bhn_[l][j]);
#pragma unroll
        for (int p = 0; p < NPAIR; p++) {
            acc[0][p] = b0; acc[1][p] = b1; acc[2][p] = b2; acc[3][p] = b3;
        }
    }
    const float* hbl = &s->hb[l][0][rh * 14];
    gemm_phase<KIN, 2>(wTi, xb,  acc, j);   // x @ wi^T -> r, z, inn
    gemm_phase<HH,  3>(wTh, hbl, acc, j);   // h @ wh^T -> r, z, hn
    __syncthreads();                        // all reads of hb[l] done
    float* hrow = &s->hb[l][j][rh * 14];
#pragma unroll
    for (int p = 0; p < NPAIR; p++) {
        float2 hold = *(const float2*)(hrow + 2 * p);
        float rlo = sigm(f2lo(acc[0][p])), rhi = sigm(f2hi(acc[0][p]));
        float ulo = sigm(f2lo(acc[1][p])), uhi = sigm(f2hi(acc[1][p]));
        float nlo = mytanh(f2lo(acc[2][p]) + rlo * f2lo(acc[3][p]));
        float nhi = mytanh(f2hi(acc[2][p]) + rhi * f2hi(acc[3][p]));
        float2 hnew;
        hnew.x = (1.0f - ulo) * nlo + ulo * hold.x;
        hnew.y = (1.0f - uhi) * nhi + uhi * hold.y;
        *(float2*)(hrow + 2 * p) = hnew;
    }
    __syncthreads();                        // new hb[l] visible
}

__global__ void __launch_bounds__(NT, 1) moldec_kernel(
    const float* __restrict__ z,     const float* __restrict__ emb,
    const float* __restrict__ z2h_b, const float* __restrict__ out_b,
    const float* __restrict__ bi0, const float* __restrict__ bh0,
    const float* __restrict__ bi1, const float* __restrict__ bh1,
    const float* __restrict__ bi2, const float* __restrict__ bh2,
    float* __restrict__ out)
{
    extern __shared__ char smraw[];
    SM* s = (SM*)smraw;
    const int tid = threadIdx.x;
    const int row0 = blockIdx.x * ROWS;
    const int j  = tid & 255;      // gate index
    const int rh = tid >> 8;       // row half (0: rows 0-13, 1: rows 14-27)

    // combined biases
    {
        const float* bip[3] = {bi0, bi1, bi2};
        const float* bhp[3] = {bh0, bh1, bh2};
        for (int i = tid; i < 3 * HH; i += NT) {
            int l = i >> 8, jj = i & 255;
            s->br[l][jj]   = bip[l][jj]          + bhp[l][jj];
            s->bz[l][jj]   = bip[l][HH + jj]     + bhp[l][HH + jj];
            s->bin_[l][jj] = bip[l][2 * HH + jj];
            s->bhn_[l][jj] = bhp[l][2 * HH + jj];
        }
    }
    // stage z transposed (k-major), zero-fill invalid rows
    for (int i = tid; i < ZZ * ROWS; i += NT) {
        int r = i / ZZ, k = i - r * ZZ;
        int grow = row0 + r;
        s->xz[k][r] = (grow < BTOT) ? z[(size_t)grow * ZZ + k] : 0.0f;
    }
    if (tid < ROWS) s->tok[tid] = 1;
    __syncthreads();

    // initial hidden: h0[l] = tanh(z @ z2h_w^T + z2h_b), sections 0,1,2 = layers
    {
        ull acc[4][NPAIR];
#pragma unroll
        for (int ss = 0; ss < 3; ss++) {
            ull b = dup2(z2h_b[ss * 256 + j]);
#pragma unroll
            for (int p = 0; p < NPAIR; p++) acc[ss][p] = b;
        }
#pragma unroll
        for (int p = 0; p < NPAIR; p++) acc[3][p] = 0ULL;
        gemm_phase<ZZ, 2>(g_z2h, &s->xz[0][rh * 14], acc, j);
#pragma unroll
        for (int ss = 0; ss < 3; ss++) {
            float* hrow = &s->hb[ss][j][rh * 14];
#pragma unroll
            for (int p = 0; p < NPAIR; p++) {
                float2 hv;
                hv.x = mytanh(f2lo(acc[ss][p]));
                hv.y = mytanh(f2hi(acc[ss][p]));
                *(float2*)(hrow + 2 * p) = hv;
            }
        }
        __syncthreads();
    }

    const float4* wTi0 = g_wT;              const float4* wTh0 = g_wT +   64 * 256;
    const float4* wTi1 = g_wT + 320 * 256;  const float4* wTh1 = g_wT +  576 * 256;
    const float4* wTi2 = g_wT + 832 * 256;  const float4* wTh2 = g_wT + 1088 * 256;

    // decode loop
    for (int t = 0; t < TS; t++) {
        // embedding gather into xz (k-major)
        for (int i = tid; i < EE * ROWS; i += NT) {
            int r = i >> 6, k = i & 63;
            s->xz[k][r] = emb[(size_t)s->tok[r] * EE + k];
        }
        __syncthreads();

        layer_stepB<EE>(s, &s->xz[0][rh * 14],       wTi0, wTh0, 0, j, rh);
        layer_stepB<HH>(s, &s->hb[0][0][rh * 14],    wTi1, wTh1, 1, j, rh);
        layer_stepB<HH>(s, &s->hb[1][0][rh * 14],    wTi2, wTh2, 2, j, rh);

        // output projection: logits = hb[2] @ out_w^T + out_b
        {
            const int v = tid & 63;
            const int g = tid >> 6;            // 8 groups; group 7 idle (28 rows)
            ull o0 = dup2(out_b[v]);
            ull o1 = o0;
            const float* xb2 = &s->hb[2][0][g * 4];
            for (int kb = 0; kb < HH; kb += 8) {
                float wreg[8];
#pragma unroll
                for (int i = 0; i < 8; i++) wreg[i] = g_owT[(kb + i) * 64 + v];
#pragma unroll
                for (int i = 0; i < 8; i++) {
                    const ull* xp = (const ull*)(xb2 + (size_t)(kb + i) * RS);
                    ull wd = dup2(wreg[i]);
                    fma2(o0, wd, xp[0]);
                    fma2(o1, wd, xp[1]);
                }
            }
            if (g < 7) {
                int r0 = g * 4;
                float l0 = f2lo(o0), l1 = f2hi(o0), l2 = f2lo(o1), l3 = f2hi(o1);
                s->lbuf[r0 + 0][v] = l0;
                s->lbuf[r0 + 1][v] = l1;
                s->lbuf[r0 + 2][v] = l2;
                s->lbuf[r0 + 3][v] = l3;
                if (row0 + r0 + 0 < BTOT) out[((size_t)(row0 + r0 + 0) * TS + t) * VV + v] = l0;
                if (row0 + r0 + 1 < BTOT) out[((size_t)(row0 + r0 + 1) * TS + t) * VV + v] = l1;
                if (row0 + r0 + 2 < BTOT) out[((size_t)(row0 + r0 + 2) * TS + t) * VV + v] = l2;
                if (row0 + r0 + 3 < BTOT) out[((size_t)(row0 + r0 + 3) * TS + t) * VV + v] = l3;
            }
        }
        __syncthreads();
        // per-row argmax (first-max tie rule)
        if (tid < ROWS) {
            float m = s->lbuf[tid][0];
            int am = 0;
#pragma unroll 8
            for (int vv = 1; vv < VV; vv++) {
                float val = s->lbuf[tid][vv];
                if (val > m) { m = val; am = vv; }
            }
            s->tok[tid] = am;
        }
        __syncthreads();
    }
}

extern "C" void kernel_launch(void* const* d_in, const int* in_sizes, int n_in,
                              void* d_out, int out_size)
{
    const float* z     = (const float*)d_in[0];
    const float* emb   = (const float*)d_in[1];
    const float* z2h_w = (const float*)d_in[2];
    const float* z2h_b = (const float*)d_in[3];
    const float* out_w = (const float*)d_in[4];
    const float* out_b = (const float*)d_in[5];
    const float* wi0 = (const float*)d_in[6];
    const float* wh0 = (const float*)d_in[7];
    const float* bi0 = (const float*)d_in[8];
    const float* bh0 = (const float*)d_in[9];
    const float* wi1 = (const float*)d_in[10];
    const float* wh1 = (const float*)d_in[11];
    const float* bi1 = (const float*)d_in[12];
    const float* bh1 = (const float*)d_in[13];
    const float* wi2 = (const float*)d_in[14];
    const float* wh2 = (const float*)d_in[15];
    const float* bi2 = (const float*)d_in[16];
    const float* bh2 = (const float*)d_in[17];
    float* out = (float*)d_out;

    prep_kernel<<<1536, 256>>>(wi0, wh0, wi1, wh1, wi2, wh2, z2h_w, out_w);

    cudaFuncSetAttribute(moldec_kernel, cudaFuncAttributeMaxDynamicSharedMemorySize,
                         (int)sizeof(SM));
    moldec_kernel<<<NCTAS, NT, sizeof(SM)>>>(
        z, emb, z2h_b, out_b,
        bi0, bh0, bi1, bh1, bi2, bh2,
        out);
}